// round 3
// baseline (speedup 1.0000x reference)
#include <cuda_runtime.h>
#include <cstdint>
#include <cfloat>

#define D 128
#define MAX_E 640000
#define MAX_N 40000
#define SCALE 0.08838834764831845f  // 1/sqrt(128)

// ---- scratch (device globals; no allocation allowed) ----
__device__ __align__(16) float g_summed[MAX_N * D];
__device__ __align__(16) float g_U[MAX_N * D];      // normalized agg
__device__ __align__(16) float g_qk[MAX_N * D];
__device__ float g_qb[MAX_N];
__device__ float g_ratio[MAX_N];                    // s/(s+1e-8)
__device__ int   g_count[MAX_N];
__device__ int   g_cursor[MAX_N];
__device__ int   g_offset[MAX_N + 1];
__device__ int   g_eidx[MAX_E];
__device__ __align__(16) float g_Mt[D * D];         // [i][l]: (Wk Wq^T)[i][l]
__device__ __align__(16) float g_Wvo[D * D];        // [j][l]: (Wv Wo)[l][j] transposed
__device__ float g_c[D];                            // Wk bq
__device__ float g_w[D];                            // Wq bk
__device__ float g_bvo[D];                          // bv Wo
__device__ float g_beta[1];                         // bk . bq

// ---- K0: fold weight matrices (tiny) ----
__global__ void k_precompute(const float* __restrict__ Wk, const float* __restrict__ bk,
                             const float* __restrict__ Wv, const float* __restrict__ bv,
                             const float* __restrict__ Wq, const float* __restrict__ bq,
                             const float* __restrict__ Wo) {
    int l = blockIdx.x;   // 0..127
    int t = threadIdx.x;  // 0..127
    if (blockIdx.y == 0) {
        // M[i=t][l] = sum_j Wk[t][j] * Wq[l][j]  -> store row-major [i][l]
        float acc = 0.f;
        for (int j = 0; j < D; j++) acc += Wk[t * D + j] * Wq[l * D + j];
        g_Mt[t * D + l] = acc;
        if (l == 0) {
            float c = 0.f, w = 0.f;
            for (int j = 0; j < D; j++) { c += Wk[t * D + j] * bq[j]; w += Wq[t * D + j] * bk[j]; }
            g_c[t] = c; g_w[t] = w;
            if (t == 0) { float b = 0.f; for (int j = 0; j < D; j++) b += bq[j] * bk[j]; g_beta[0] = b; }
        }
    } else {
        // Wvo[l][j=t] = sum_i Wv[l][i] * Wo[i][t]  -> store transposed [j][l]
        float acc = 0.f;
        for (int i = 0; i < D; i++) acc += Wv[l * D + i] * Wo[i * D + t];
        g_Wvo[t * D + l] = acc;
        if (l == 0) {
            float b = 0.f;
            for (int i = 0; i < D; i++) b += bv[i] * Wo[i * D + t];
            g_bvo[t] = b;
        }
    }
}

// ---- K1: zero counters (graph replays re-run everything) ----
__global__ void k_init(int N) {
    int i = blockIdx.x * blockDim.x + threadIdx.x;
    if (i < N) { g_count[i] = 0; g_cursor[i] = 0; }
}

// ---- K2: histogram of receivers ----
__global__ void k_hist(const int* __restrict__ recv, int E) {
    int e = blockIdx.x * blockDim.x + threadIdx.x;
    if (e < E) atomicAdd(&g_count[recv[e]], 1);
}

// ---- K3: exclusive prefix scan (single block, 1024 threads) ----
__global__ void k_scan(int N) {
    __shared__ int warp_sums[32];
    int tid = threadIdx.x;
    int CH = (N + 1023) / 1024;
    int start = tid * CH;
    int s = 0;
    for (int i = 0; i < CH; i++) { int idx = start + i; if (idx < N) s += g_count[idx]; }
    int lane = tid & 31, wid = tid >> 5;
    int v = s;
    #pragma unroll
    for (int o = 1; o < 32; o <<= 1) { int t2 = __shfl_up_sync(0xffffffffu, v, o); if (lane >= o) v += t2; }
    if (lane == 31) warp_sums[wid] = v;
    __syncthreads();
    if (wid == 0) {
        int w = warp_sums[lane];
        #pragma unroll
        for (int o = 1; o < 32; o <<= 1) { int t2 = __shfl_up_sync(0xffffffffu, w, o); if (lane >= o) w += t2; }
        warp_sums[lane] = w;
    }
    __syncthreads();
    int excl = v - s + (wid > 0 ? warp_sums[wid - 1] : 0);
    int run = excl;
    for (int i = 0; i < CH; i++) {
        int idx = start + i;
        if (idx < N) { g_offset[idx] = run; run += g_count[idx]; }
    }
    if (tid == 1023) g_offset[N] = run;
}

// ---- K4: scatter edge ids into sorted order ----
__global__ void k_scatter(const int* __restrict__ recv, int E) {
    int e = blockIdx.x * blockDim.x + threadIdx.x;
    if (e < E) {
        int r = recv[e];
        int pos = g_offset[r] + atomicAdd(&g_cursor[r], 1);
        g_eidx[pos] = e;
    }
}

// ---- K5: segment sum of messages, warp per node, no atomics ----
__global__ void k_segsum(const float4* __restrict__ msg, int N) {
    int idx = blockIdx.x * blockDim.x + threadIdx.x;
    int n = idx >> 5, lane = idx & 31;
    if (n >= N) return;
    int beg = g_offset[n], end = g_offset[n + 1];
    float4 a0 = make_float4(0.f, 0.f, 0.f, 0.f);
    float4 a1 = make_float4(0.f, 0.f, 0.f, 0.f);
    int i = beg;
    for (; i + 1 < end; i += 2) {
        int e0 = g_eidx[i], e1 = g_eidx[i + 1];
        float4 m0 = __ldg(&msg[(size_t)e0 * 32 + lane]);
        float4 m1 = __ldg(&msg[(size_t)e1 * 32 + lane]);
        a0.x += m0.x; a0.y += m0.y; a0.z += m0.z; a0.w += m0.w;
        a1.x += m1.x; a1.y += m1.y; a1.z += m1.z; a1.w += m1.w;
    }
    if (i < end) {
        int e0 = g_eidx[i];
        float4 m0 = __ldg(&msg[(size_t)e0 * 32 + lane]);
        a0.x += m0.x; a0.y += m0.y; a0.z += m0.z; a0.w += m0.w;
    }
    a0.x += a1.x; a0.y += a1.y; a0.z += a1.z; a0.w += a1.w;
    reinterpret_cast<float4*>(g_summed)[n * 32 + lane] = a0;
}

// ---- K6: qk[n] = M @ summed[n] + c ; qb[n] = w . summed[n] + beta ----
__global__ void k_qk(int N) {
    __shared__ float sh2[D][8];  // [l][k]
    int nb = blockIdx.x * 8;
    int t = threadIdx.x;
    #pragma unroll
    for (int k = 0; k < 8; k++) {
        int n = nb + k;
        sh2[t][k] = (n < N) ? g_summed[n * D + t] : 0.f;
    }
    __syncthreads();
    float acc[8];
    float cc = g_c[t];
    #pragma unroll
    for (int k = 0; k < 8; k++) acc[k] = cc;
    const float4* mrow = reinterpret_cast<const float4*>(&g_Mt[t * D]);
    for (int l4 = 0; l4 < D / 4; l4++) {
        float4 mt = mrow[l4];
        float mv[4] = {mt.x, mt.y, mt.z, mt.w};
        #pragma unroll
        for (int dl = 0; dl < 4; dl++) {
            int l = l4 * 4 + dl;
            float4 a = *reinterpret_cast<const float4*>(&sh2[l][0]);
            float4 b = *reinterpret_cast<const float4*>(&sh2[l][4]);
            float m = mv[dl];
            acc[0] += m * a.x; acc[1] += m * a.y; acc[2] += m * a.z; acc[3] += m * a.w;
            acc[4] += m * b.x; acc[5] += m * b.y; acc[6] += m * b.z; acc[7] += m * b.w;
        }
    }
    #pragma unroll
    for (int k = 0; k < 8; k++) {
        int n = nb + k;
        if (n < N) g_qk[n * D + t] = acc[k];
    }
    if (t < 8) {
        int n = nb + t;
        if (n < N) {
            float q = g_beta[0];
            for (int l = 0; l < D; l++) q += g_w[l] * sh2[l][t];
            g_qb[n] = q;
        }
    }
}

__device__ __forceinline__ float dot4(float4 a, float4 b) {
    return a.x * b.x + a.y * b.y + a.z * b.z + a.w * b.w;
}

// ---- K7: fused scores + online softmax + weighted aggregation ----
__global__ void k_attn(const float4* __restrict__ msg, int N) {
    int idx = blockIdx.x * blockDim.x + threadIdx.x;
    int n = idx >> 5, lane = idx & 31;
    if (n >= N) return;
    int beg = g_offset[n], end = g_offset[n + 1];
    float4 q4 = reinterpret_cast<const float4*>(g_qk)[n * 32 + lane];
    float qb = g_qb[n];
    float mrun = -FLT_MAX, s = 0.f;
    float4 u = make_float4(0.f, 0.f, 0.f, 0.f);
    int i = beg;
    for (; i + 1 < end; i += 2) {
        int e0 = g_eidx[i], e1 = g_eidx[i + 1];
        float4 m0 = __ldg(&msg[(size_t)e0 * 32 + lane]);
        float4 m1 = __ldg(&msg[(size_t)e1 * 32 + lane]);
        float d0 = dot4(m0, q4), d1 = dot4(m1, q4);
        #pragma unroll
        for (int o = 16; o > 0; o >>= 1) {
            d0 += __shfl_xor_sync(0xffffffffu, d0, o);
            d1 += __shfl_xor_sync(0xffffffffu, d1, o);
        }
        float s0 = (d0 + qb) * SCALE;
        float s1 = (d1 + qb) * SCALE;
        float nm = fmaxf(mrun, fmaxf(s0, s1));
        float f = __expf(mrun - nm);
        float w0 = __expf(s0 - nm);
        float w1 = __expf(s1 - nm);
        s = s * f + w0 + w1;
        u.x = u.x * f + w0 * m0.x + w1 * m1.x;
        u.y = u.y * f + w0 * m0.y + w1 * m1.y;
        u.z = u.z * f + w0 * m0.z + w1 * m1.z;
        u.w = u.w * f + w0 * m0.w + w1 * m1.w;
        mrun = nm;
    }
    if (i < end) {
        int e0 = g_eidx[i];
        float4 m0 = __ldg(&msg[(size_t)e0 * 32 + lane]);
        float d0 = dot4(m0, q4);
        #pragma unroll
        for (int o = 16; o > 0; o >>= 1) d0 += __shfl_xor_sync(0xffffffffu, d0, o);
        float s0 = (d0 + qb) * SCALE;
        float nm = fmaxf(mrun, s0);
        float f = __expf(mrun - nm);
        float w0 = __expf(s0 - nm);
        s = s * f + w0;
        u.x = u.x * f + w0 * m0.x;
        u.y = u.y * f + w0 * m0.y;
        u.z = u.z * f + w0 * m0.z;
        u.w = u.w * f + w0 * m0.w;
        mrun = nm;
    }
    float inv = 1.f / (s + 1e-8f);
    u.x *= inv; u.y *= inv; u.z *= inv; u.w *= inv;
    reinterpret_cast<float4*>(g_U)[n * 32 + lane] = u;
    if (lane == 0) g_ratio[n] = s * inv;
}

// ---- K8: out[n] = agg[n] @ Wvo + ratio*bvo + bo ----
__global__ void k_out(const float* __restrict__ bo, float* __restrict__ out, int N) {
    __shared__ float sh2[D][8];
    __shared__ float sa[8];
    int nb = blockIdx.x * 8;
    int t = threadIdx.x;
    #pragma unroll
    for (int k = 0; k < 8; k++) {
        int n = nb + k;
        sh2[t][k] = (n < N) ? g_U[n * D + t] : 0.f;
        if (t == 0) sa[k] = (n < N) ? g_ratio[n] : 0.f;
    }
    __syncthreads();
    float bj = __ldg(&bo[t]);
    float bvoj = g_bvo[t];
    float acc[8];
    #pragma unroll
    for (int k = 0; k < 8; k++) acc[k] = bj;
    #pragma unroll
    for (int k = 0; k < 8; k++) acc[k] += sa[k] * bvoj;
    const float4* wrow = reinterpret_cast<const float4*>(&g_Wvo[t * D]);
    for (int l4 = 0; l4 < D / 4; l4++) {
        float4 wt = wrow[l4];
        float wv[4] = {wt.x, wt.y, wt.z, wt.w};
        #pragma unroll
        for (int dl = 0; dl < 4; dl++) {
            int l = l4 * 4 + dl;
            float4 a = *reinterpret_cast<const float4*>(&sh2[l][0]);
            float4 b = *reinterpret_cast<const float4*>(&sh2[l][4]);
            float m = wv[dl];
            acc[0] += m * a.x; acc[1] += m * a.y; acc[2] += m * a.z; acc[3] += m * a.w;
            acc[4] += m * b.x; acc[5] += m * b.y; acc[6] += m * b.z; acc[7] += m * b.w;
        }
    }
    #pragma unroll
    for (int k = 0; k < 8; k++) {
        int n = nb + k;
        if (n < N) out[n * D + t] = acc[k];
    }
}

extern "C" void kernel_launch(void* const* d_in, const int* in_sizes, int n_in,
                              void* d_out, int out_size) {
    const float* messages = (const float*)d_in[0];
    const int*   receivers = (const int*)d_in[1];
    int base = (n_in >= 11 && in_sizes[2] == 1) ? 3 : 2;
    const float* Wk = (const float*)d_in[base + 0];
    const float* bk = (const float*)d_in[base + 1];
    const float* Wv = (const float*)d_in[base + 2];
    const float* bv = (const float*)d_in[base + 3];
    const float* Wq = (const float*)d_in[base + 4];
    const float* bq = (const float*)d_in[base + 5];
    const float* Wo = (const float*)d_in[base + 6];
    const float* bo = (const float*)d_in[base + 7];

    int E = in_sizes[1];
    int N = out_size / D;
    float* out = (float*)d_out;

    k_precompute<<<dim3(D, 2), D>>>(Wk, bk, Wv, bv, Wq, bq, Wo);
    k_init<<<(N + 255) / 256, 256>>>(N);
    k_hist<<<(E + 255) / 256, 256>>>(receivers, E);
    k_scan<<<1, 1024>>>(N);
    k_scatter<<<(E + 255) / 256, 256>>>(receivers, E);
    int nwarp_blocks = (N * 32 + 255) / 256;
    k_segsum<<<nwarp_blocks, 256>>>((const float4*)messages, N);
    k_qk<<<(N + 7) / 8, D>>>(N);
    k_attn<<<nwarp_blocks, 256>>>((const float4*)messages, N);
    k_out<<<(N + 7) / 8, D>>>(bo, out, N);
}